// round 1
// baseline (speedup 1.0000x reference)
#include <cuda_runtime.h>
#include <math.h>

#define B_TOT   32768
#define T_STEPS 32
#define HID     128
#define GATES   512
#define OBS_OS  8
#define OBS_TS  6
#define SDIM    200     // 8 + 32*6
#define NACT    9
#define M_TILE  32
#define NTHREADS 512
#define NCTA    (B_TOT / M_TILE)

// ---------------- scratch (no allocations allowed) ----------------
__device__ int g_nobs[B_TOT];
__device__ int g_perm[B_TOT];
__device__ int g_hist[T_STEPS + 1];
__device__ int g_cursor[T_STEPS + 1];

// ---------------- shared-memory layout (float offsets) ----------------
// buf: W-chunk staging (stride 36 -> conflict-free LDS.128) AND gate-exchange buffer
#define O_BUF   0
#define SZ_BUF  (512 * 36)
#define O_SH    (O_BUF + SZ_BUF)          // h:   [m][132]  (pad for 16B align, bcast reads)
#define O_SC    (O_SH + 32 * 132)         // c:   [jh][36]
#define O_SHOUT (O_SC + 128 * 36)         // hout:[m][128]
#define O_XCAT  (O_SHOUT + 32 * 128)      // xcat:[m][256]
#define O_C1    (O_XCAT + 32 * 256)       // c1:  [m][132]
#define O_X     (O_C1 + 32 * 132)         // x_t: [m][8]
#define O_X2    (O_X + 32 * 8)            // s_OS:[m][8]
#define O_WC2   (O_X2 + 32 * 8)           // W_c2:[o][132]
#define O_INT   (O_WC2 + 9 * 132)         // ints: nobs[32], samp[32]
#define SMEM_FLOATS (O_INT + 64)
#define SMEM_BYTES  (SMEM_FLOATS * 4)

__device__ __forceinline__ float sigf(float x) {
    float e = __expf(-x);
    return __fdividef(1.0f, 1.0f + e);
}
__device__ __forceinline__ float tanh_a(float x) {
    return 2.0f * sigf(2.0f * x) - 1.0f;
}

// ---------------- pre-pass: length bucketing ----------------
__global__ void k_zero() {
    int t = threadIdx.x;
    if (t <= T_STEPS) g_hist[t] = 0;
}

__global__ void k_count(const float* __restrict__ s) {
    int m = blockIdx.x * blockDim.x + threadIdx.x;
    if (m >= B_TOT) return;
    const float* p = s + m * SDIM + OBS_OS;
    int cnt = 0;
#pragma unroll
    for (int t = 0; t < T_STEPS; ++t) {
        float v = p[t * OBS_TS];
        cnt += (v == v) ? 1 : 0;   // !isnan
    }
    g_nobs[m] = cnt;
    atomicAdd(&g_hist[cnt], 1);
}

__global__ void k_prefix() {
    // descending length order: longest tiles scheduled first (tail balance)
    int off = 0;
    for (int len = T_STEPS; len >= 0; --len) {
        g_cursor[len] = off;
        off += g_hist[len];
    }
}

__global__ void k_scatter() {
    int m = blockIdx.x * blockDim.x + threadIdx.x;
    if (m >= B_TOT) return;
    int pos = atomicAdd(&g_cursor[g_nobs[m]], 1);
    g_perm[pos] = m;
}

// ---------------- fused main kernel ----------------
__global__ void __launch_bounds__(NTHREADS, 1)
k_main(const float* __restrict__ s,
       const float* __restrict__ W_os, const float* __restrict__ b_os,
       const float* __restrict__ W_ih, const float* __restrict__ W_hh,
       const float* __restrict__ b_ih, const float* __restrict__ b_hh,
       const float* __restrict__ W_ts, const float* __restrict__ b_ts,
       const float* __restrict__ W_c1, const float* __restrict__ b_c1,
       const float* __restrict__ W_c2, const float* __restrict__ b_c2,
       float* __restrict__ out)
{
    extern __shared__ float sm[];
    float* sW    = sm + O_BUF;
    float* sH    = sm + O_SH;
    float* sC    = sm + O_SC;
    float* sHout = sm + O_SHOUT;
    float* sXcat = sm + O_XCAT;
    float* sC1o  = sm + O_C1;
    float* sX    = sm + O_X;
    float* sX2   = sm + O_X2;
    float* sWc2  = sm + O_WC2;
    int*   sNobs = (int*)(sm + O_INT);
    int*   sSamp = sNobs + 32;
    __shared__ int sTmaxS;

    const int tid = threadIdx.x;
    const int j   = tid;          // owned gate row (0..511)
    const int jh  = tid & 127;    // hidden unit
    const int mg  = tid >> 7;     // sample group (0..3)
    const int base = blockIdx.x * M_TILE;

    if (tid < M_TILE) {
        int idx = g_perm[base + tid];
        sSamp[tid] = idx;
        sNobs[tid] = g_nobs[idx];
    }
    for (int i = tid; i < 32 * 132; i += NTHREADS) sH[i] = 0.0f;
    for (int i = tid; i < 128 * 36; i += NTHREADS) sC[i] = 0.0f;
    for (int i = tid; i < 32 * 128; i += NTHREADS) sHout[i] = 0.0f;
    __syncthreads();
    if (tid == 0) {
        int tm = 0;
        for (int m = 0; m < M_TILE; ++m) tm = max(tm, sNobs[m]);
        sTmaxS = tm;
    }

    // per-thread LSTM input weights + fused bias for owned gate row
    float wih[OBS_TS];
#pragma unroll
    for (int i = 0; i < OBS_TS; ++i) wih[i] = W_ih[j * OBS_TS + i];
    const float bias = b_ih[j] + b_hh[j];
    __syncthreads();
    const int tmax = sTmaxS;

    // ================= LSTM recurrence =================
    for (int t = 0; t < tmax; ++t) {
        // stage x_t (NaN -> 0)
        if (tid < M_TILE * OBS_TS) {
            int m = tid / OBS_TS, i = tid - m * OBS_TS;
            float v = s[sSamp[m] * SDIM + OBS_OS + t * OBS_TS + i];
            sX[m * 8 + i] = (v == v) ? v : 0.0f;
        }
        __syncthreads();

        float acc[M_TILE];
#pragma unroll
        for (int m = 0; m < M_TILE; ++m) {
            float a = bias;
#pragma unroll
            for (int i = 0; i < OBS_TS; ++i) a = fmaf(wih[i], sX[m * 8 + i], a);
            acc[m] = a;
        }

        // gates += h @ W_hh^T, K staged in 4 chunks of 32
#pragma unroll 1
        for (int c = 0; c < 4; ++c) {
            __syncthreads();   // protect buf from previous users
            {
                const float4* src = (const float4*)(W_hh + j * HID + c * 32);
                float4* dst = (float4*)(sW + j * 36);
#pragma unroll
                for (int q = 0; q < 8; ++q) dst[q] = src[q];
            }
            __syncthreads();
#pragma unroll 1
            for (int kk = 0; kk < 8; ++kk) {
                float4 w = *(const float4*)(sW + j * 36 + kk * 4);
                int k = c * 32 + kk * 4;
#pragma unroll
                for (int m = 0; m < M_TILE; ++m) {
                    float4 h = *(const float4*)(sH + m * 132 + k);  // uniform bcast
                    float a = acc[m];
                    a = fmaf(w.x, h.x, a);
                    a = fmaf(w.y, h.y, a);
                    a = fmaf(w.z, h.z, a);
                    a = fmaf(w.w, h.w, a);
                    acc[m] = a;
                }
            }
        }
        __syncthreads();
        // exchange preacts: buf reused as sG[j][m] (stride 36)
        {
            float4* dst = (float4*)(sW + j * 36);
#pragma unroll
            for (int q = 0; q < 8; ++q)
                dst[q] = make_float4(acc[q * 4], acc[q * 4 + 1], acc[q * 4 + 2], acc[q * 4 + 3]);
        }
        __syncthreads();
        // gate nonlinearities + state update: thread -> (jh, 8 samples)
#pragma unroll
        for (int mm = 0; mm < 8; ++mm) {
            int m = mg * 8 + mm;
            float gi = sW[(jh      ) * 36 + m];
            float gf = sW[(jh + 128) * 36 + m];
            float gg = sW[(jh + 256) * 36 + m];
            float go = sW[(jh + 384) * 36 + m];
            float iv = sigf(gi), fv = sigf(gf), gv = tanh_a(gg), ov = sigf(go);
            float cv = fmaf(fv, sC[jh * 36 + m], iv * gv);
            sC[jh * 36 + m] = cv;
            float hv = ov * tanh_a(cv);
            sH[m * 132 + jh] = hv;
            if (t == sNobs[m] - 1) sHout[m * 128 + jh] = hv;   // snapshot at h_idx
        }
        __syncthreads();
    }

    // ================= head =================
    // stage s_OS and small weights
    if (tid < M_TILE * OBS_OS) {
        int m = tid >> 3, i = tid & 7;
        sX2[tid] = s[sSamp[m] * SDIM + i];
    }
    {   // stage W_ts -> buf [jh][132]
        const float4* src = (const float4*)(W_ts + jh * HID + mg * 32);
        float4* dst = (float4*)(sW + jh * 132 + mg * 32);
#pragma unroll
        for (int r = 0; r < 8; ++r) dst[r] = src[r];
    }
    if (tid < NACT * 32) {   // stage W_c2 -> [o][132]
        int o = tid >> 5, kb = (tid & 31) * 4;
        *(float4*)(sWc2 + o * 132 + kb) = *(const float4*)(W_c2 + o * HID + kb);
    }
    __syncthreads();

    // x_OS = relu(s_OS @ W_os^T + b_os) -> xcat[:, 0:128]
    {
        float wos[8];
#pragma unroll
        for (int i = 0; i < 8; ++i) wos[i] = W_os[jh * 8 + i];
        float bos = b_os[jh];
#pragma unroll
        for (int mm = 0; mm < 8; ++mm) {
            int m = mg * 8 + mm;
            float a = bos;
#pragma unroll
            for (int i = 0; i < 8; ++i) a = fmaf(wos[i], sX2[m * 8 + i], a);
            sXcat[m * 256 + jh] = fmaxf(a, 0.0f);
        }
    }
    // x_TS = relu(hout @ W_ts^T + b_ts) -> xcat[:, 128:256]
    {
        float a8[8] = {0, 0, 0, 0, 0, 0, 0, 0};
#pragma unroll 1
        for (int k4 = 0; k4 < 32; ++k4) {
            float4 w = *(const float4*)(sW + jh * 132 + k4 * 4);
#pragma unroll
            for (int mm = 0; mm < 8; ++mm) {
                int m = mg * 8 + mm;
                float4 h = *(const float4*)(sHout + m * 128 + k4 * 4);
                float a = a8[mm];
                a = fmaf(w.x, h.x, a);
                a = fmaf(w.y, h.y, a);
                a = fmaf(w.z, h.z, a);
                a = fmaf(w.w, h.w, a);
                a8[mm] = a;
            }
        }
        float bts = b_ts[jh];
#pragma unroll
        for (int mm = 0; mm < 8; ++mm) {
            int m = mg * 8 + mm;
            sXcat[m * 256 + HID + jh] = fmaxf(a8[mm] + bts, 0.0f);
        }
    }
    __syncthreads();

    // c1 = relu(xcat @ W_c1^T + b_c1), K=256 in two staged halves
    {
        float a8[8] = {0, 0, 0, 0, 0, 0, 0, 0};
#pragma unroll 1
        for (int half = 0; half < 2; ++half) {
            __syncthreads();
            {
                const float4* src = (const float4*)(W_c1 + jh * 256 + half * 128 + mg * 32);
                float4* dst = (float4*)(sW + jh * 132 + mg * 32);
#pragma unroll
                for (int r = 0; r < 8; ++r) dst[r] = src[r];
            }
            __syncthreads();
#pragma unroll 1
            for (int k4 = 0; k4 < 32; ++k4) {
                float4 w = *(const float4*)(sW + jh * 132 + k4 * 4);
#pragma unroll
                for (int mm = 0; mm < 8; ++mm) {
                    int m = mg * 8 + mm;
                    float4 x = *(const float4*)(sXcat + m * 256 + half * 128 + k4 * 4);
                    float a = a8[mm];
                    a = fmaf(w.x, x.x, a);
                    a = fmaf(w.y, x.y, a);
                    a = fmaf(w.z, x.z, a);
                    a = fmaf(w.w, x.w, a);
                    a8[mm] = a;
                }
            }
        }
        float bc1 = b_c1[jh];
#pragma unroll
        for (int mm = 0; mm < 8; ++mm) {
            int m = mg * 8 + mm;
            sC1o[m * 132 + jh] = fmaxf(a8[mm] + bc1, 0.0f);
        }
    }
    __syncthreads();

    // out = c1 @ W_c2^T + b_c2  (9 outputs/sample)
    if (tid < M_TILE * NACT) {
        int m = tid / NACT, o = tid - m * NACT;
        float a = b_c2[o];
#pragma unroll 1
        for (int k4 = 0; k4 < 32; ++k4) {
            float4 w = *(const float4*)(sWc2 + o * 132 + k4 * 4);
            float4 x = *(const float4*)(sC1o + m * 132 + k4 * 4);
            a = fmaf(w.x, x.x, a);
            a = fmaf(w.y, x.y, a);
            a = fmaf(w.z, x.z, a);
            a = fmaf(w.w, x.w, a);
        }
        out[sSamp[m] * NACT + o] = a;
    }
}

// ---------------- launch ----------------
extern "C" void kernel_launch(void* const* d_in, const int* in_sizes, int n_in,
                              void* d_out, int out_size) {
    const float* s    = (const float*)d_in[0];
    const float* W_os = (const float*)d_in[1];
    const float* b_os = (const float*)d_in[2];
    const float* W_ih = (const float*)d_in[3];
    const float* W_hh = (const float*)d_in[4];
    const float* b_ih = (const float*)d_in[5];
    const float* b_hh = (const float*)d_in[6];
    const float* W_ts = (const float*)d_in[7];
    const float* b_ts = (const float*)d_in[8];
    const float* W_c1 = (const float*)d_in[9];
    const float* b_c1 = (const float*)d_in[10];
    const float* W_c2 = (const float*)d_in[11];
    const float* b_c2 = (const float*)d_in[12];
    float* out = (float*)d_out;

    cudaFuncSetAttribute(k_main, cudaFuncAttributeMaxDynamicSharedMemorySize, SMEM_BYTES);

    k_zero<<<1, 64>>>();
    k_count<<<B_TOT / 256, 256>>>(s);
    k_prefix<<<1, 1>>>();
    k_scatter<<<B_TOT / 256, 256>>>();
    k_main<<<NCTA, NTHREADS, SMEM_BYTES>>>(s, W_os, b_os, W_ih, W_hh, b_ih, b_hh,
                                           W_ts, b_ts, W_c1, b_c1, W_c2, b_c2, out);
}